// round 12
// baseline (speedup 1.0000x reference)
#include <cuda_runtime.h>
#include <math.h>
#include <stdint.h>

// ---------------- problem dims (hardcoded, verified vs reference) ----------
static constexpr int kB   = 2;
static constexpr int kS   = 2048;
static constexpr int kD   = 2048;
static constexpr int kH   = 16;
static constexpr int kHD  = 128;     // kD / kH
static constexpr int kDFF = 8192;    // 4 * kD
static constexpr int kRows = kB * kS;            // 4096
static constexpr float kEPS = 1e-5f;

// ---------------- scratch (device globals; no allocations allowed) --------
__device__ float g_buf_h [(size_t)kRows * kD];    // LN1 out -> later attn out
__device__ float g_buf_q [(size_t)kRows * kD];    // q -> later h2 (LN2 out)
__device__ float g_buf_k [(size_t)kRows * kD];
__device__ float g_buf_v [(size_t)kRows * kD];
__device__ float g_buf_x1[(size_t)kRows * kD];    // x + attn@wo
__device__ float g_buf_ff[(size_t)kRows * kDFF];  // GELU(h2@w1+b1)

// ===========================================================================
// LayerNorm: one block per row, D=2048, 256 threads, 8 floats/thread in regs
// ===========================================================================
__global__ void __launch_bounds__(256) ln_kernel(const float* __restrict__ x,
                                                 const float* __restrict__ g,
                                                 const float* __restrict__ b,
                                                 float* __restrict__ y)
{
    __shared__ float red1[8];
    __shared__ float red2[8];
    __shared__ float bc1, bc2;

    const int row = blockIdx.x;
    const int t   = threadIdx.x;

    const float4* xr = (const float4*)(x + (size_t)row * kD);
    float4 v0 = xr[t];
    float4 v1 = xr[t + 256];

    float s = v0.x + v0.y + v0.z + v0.w + v1.x + v1.y + v1.z + v1.w;
    #pragma unroll
    for (int o = 16; o; o >>= 1) s += __shfl_xor_sync(0xffffffffu, s, o);
    if ((t & 31) == 0) red1[t >> 5] = s;
    __syncthreads();
    if (t == 0) {
        float tot = 0.f;
        #pragma unroll
        for (int i = 0; i < 8; ++i) tot += red1[i];
        bc1 = tot * (1.0f / kD);
    }
    __syncthreads();
    const float mu = bc1;

    float d0 = v0.x - mu, d1 = v0.y - mu, d2 = v0.z - mu, d3 = v0.w - mu;
    float d4 = v1.x - mu, d5 = v1.y - mu, d6 = v1.z - mu, d7 = v1.w - mu;
    float ss = d0*d0 + d1*d1 + d2*d2 + d3*d3 + d4*d4 + d5*d5 + d6*d6 + d7*d7;
    #pragma unroll
    for (int o = 16; o; o >>= 1) ss += __shfl_xor_sync(0xffffffffu, ss, o);
    if ((t & 31) == 0) red2[t >> 5] = ss;
    __syncthreads();
    if (t == 0) {
        float tot = 0.f;
        #pragma unroll
        for (int i = 0; i < 8; ++i) tot += red2[i];
        bc2 = rsqrtf(tot * (1.0f / kD) + kEPS);
    }
    __syncthreads();
    const float rs = bc2;

    const float4* gr = (const float4*)g;
    const float4* br = (const float4*)b;
    float4 g0 = gr[t], g1 = gr[t + 256];
    float4 b0 = br[t], b1 = br[t + 256];

    float4 o0, o1;
    o0.x = d0 * rs * g0.x + b0.x;  o0.y = d1 * rs * g0.y + b0.y;
    o0.z = d2 * rs * g0.z + b0.z;  o0.w = d3 * rs * g0.w + b0.w;
    o1.x = d4 * rs * g1.x + b1.x;  o1.y = d5 * rs * g1.y + b1.y;
    o1.z = d6 * rs * g1.z + b1.z;  o1.w = d7 * rs * g1.w + b1.w;

    float4* yr = (float4*)(y + (size_t)row * kD);
    yr[t]       = o0;
    yr[t + 256] = o1;
}

// ===========================================================================
// SGEMM: C[M,N] = A[M,K] @ W[K,N] (+ epilogue)
//   128x128 block tile, 16 k-tile, 256 threads, 8x8 microtile, double buffer.
//   EPI 0: +bias   EPI 1: +bias+res   EPI 2: gelu(+bias)
//   Requires M%128==0, N%128==0, K%16==0 (true for all uses here).
// ===========================================================================
__device__ __forceinline__ float gelu_f(float v) {
    return 0.5f * v * (1.0f + erff(v * 0.70710678118654752440f));
}

template<int EPI>
__global__ void __launch_bounds__(256, 2) sgemm_kernel(
    const float* __restrict__ A, const float* __restrict__ W,
    const float* __restrict__ bias, const float* __restrict__ res,
    float* __restrict__ C, int M, int N, int K)
{
    __shared__ __align__(16) float As[2][16][132];   // transposed A tile
    __shared__ __align__(16) float Bs[2][16][132];

    const int t  = threadIdx.x;
    const int bm = blockIdx.y << 7;
    const int bn = blockIdx.x << 7;

    // global load mapping
    const int ar = t >> 2;            // 0..63
    const int ac = (t & 3) << 2;      // 0,4,8,12
    const int br = t >> 5;            // 0..7
    const int bc = (t & 31) << 2;     // 0..124
    const float* Ap  = A + (size_t)(bm + ar) * K + ac;
    const float* Ap2 = Ap + (size_t)64 * K;
    const float* Bp  = W + (size_t)br * N + bn + bc;
    const float* Bp2 = Bp + (size_t)8 * N;

    // compute mapping
    const int tm = (t & 15) << 3;     // row offset
    const int tn = (t >> 4) << 3;     // col offset

    float acc[8][8];
    #pragma unroll
    for (int i = 0; i < 8; ++i)
        #pragma unroll
        for (int j = 0; j < 8; ++j) acc[i][j] = 0.f;

    // prologue: tile 0 -> smem buf 0
    {
        float4 a0 = *(const float4*)Ap;
        float4 a1 = *(const float4*)Ap2;
        float4 b0 = *(const float4*)Bp;
        float4 b1 = *(const float4*)Bp2;
        As[0][ac+0][ar]    = a0.x; As[0][ac+1][ar]    = a0.y;
        As[0][ac+2][ar]    = a0.z; As[0][ac+3][ar]    = a0.w;
        As[0][ac+0][ar+64] = a1.x; As[0][ac+1][ar+64] = a1.y;
        As[0][ac+2][ar+64] = a1.z; As[0][ac+3][ar+64] = a1.w;
        *(float4*)&Bs[0][br][bc]     = b0;
        *(float4*)&Bs[0][br + 8][bc] = b1;
    }
    __syncthreads();

    const int KT = K >> 4;
    int cur = 0;
    for (int kt = 0; kt < KT; ++kt) {
        float4 na0, na1, nb0, nb1;
        const bool has_next = (kt + 1 < KT);
        if (has_next) {
            const float* ap = Ap + ((kt + 1) << 4);
            na0 = *(const float4*)ap;
            na1 = *(const float4*)(ap + (size_t)64 * K);
            const float* bp = Bp + (size_t)((kt + 1) << 4) * N;
            nb0 = *(const float4*)bp;
            nb1 = *(const float4*)(bp + (size_t)8 * N);
        }

        #pragma unroll
        for (int k = 0; k < 16; ++k) {
            float a[8], w[8];
            *(float4*)&a[0] = *(const float4*)&As[cur][k][tm];
            *(float4*)&a[4] = *(const float4*)&As[cur][k][tm + 4];
            *(float4*)&w[0] = *(const float4*)&Bs[cur][k][tn];
            *(float4*)&w[4] = *(const float4*)&Bs[cur][k][tn + 4];
            #pragma unroll
            for (int i = 0; i < 8; ++i)
                #pragma unroll
                for (int j = 0; j < 8; ++j)
                    acc[i][j] = fmaf(a[i], w[j], acc[i][j]);
        }

        if (has_next) {
            const int nxt = cur ^ 1;
            As[nxt][ac+0][ar]    = na0.x; As[nxt][ac+1][ar]    = na0.y;
            As[nxt][ac+2][ar]    = na0.z; As[nxt][ac+3][ar]    = na0.w;
            As[nxt][ac+0][ar+64] = na1.x; As[nxt][ac+1][ar+64] = na1.y;
            As[nxt][ac+2][ar+64] = na1.z; As[nxt][ac+3][ar+64] = na1.w;
            *(float4*)&Bs[nxt][br][bc]     = nb0;
            *(float4*)&Bs[nxt][br + 8][bc] = nb1;
            __syncthreads();
            cur = nxt;
        }
    }

    // epilogue
    float bv[8];
    *(float4*)&bv[0] = *(const float4*)&bias[bn + tn];
    *(float4*)&bv[4] = *(const float4*)&bias[bn + tn + 4];

    #pragma unroll
    for (int i = 0; i < 8; ++i) {
        const size_t off = (size_t)(bm + tm + i) * N + bn + tn;
        float o[8];
        #pragma unroll
        for (int j = 0; j < 8; ++j) o[j] = acc[i][j] + bv[j];
        if (EPI == 1) {
            float rv[8];
            *(float4*)&rv[0] = *(const float4*)(res + off);
            *(float4*)&rv[4] = *(const float4*)(res + off + 4);
            #pragma unroll
            for (int j = 0; j < 8; ++j) o[j] += rv[j];
        } else if (EPI == 2) {
            #pragma unroll
            for (int j = 0; j < 8; ++j) o[j] = gelu_f(o[j]);
        }
        *(float4*)(C + off)     = *(float4*)&o[0];
        *(float4*)(C + off + 4) = *(float4*)&o[4];
    }
}

// ===========================================================================
// Flash attention (causal + key-pad mask), fp32, online softmax.
//   Per block: one (b, h, q-tile of 64). BK=64, HD=128. 256 threads.
//   Q/K/V layout: [B, S, H*HD] (head h lives at cols h*128..h*128+127).
// ===========================================================================
static constexpr int QS_STRIDE = 129;
static constexpr int KS_STRIDE = 129;
static constexpr int VS_STRIDE = 132;  // 16B-aligned rows for float4 loads
static constexpr int PS_STRIDE = 65;
static constexpr int FLASH_SMEM_FLOATS =
    64 * QS_STRIDE + 64 * KS_STRIDE + 64 * VS_STRIDE + 64 * PS_STRIDE + 5 * 64 + 64;
static constexpr int FLASH_SMEM_BYTES = FLASH_SMEM_FLOATS * 4; // 118016

__global__ void __launch_bounds__(256) flash_kernel(
    const float* __restrict__ Q, const float* __restrict__ Kg,
    const float* __restrict__ Vg, const int* __restrict__ am,
    float* __restrict__ Og)
{
    extern __shared__ float sm[];
    float* Qs    = sm;
    float* Ks    = Qs + 64 * QS_STRIDE;
    float* Vs    = Ks + 64 * KS_STRIDE;
    float* Ps    = Vs + 64 * VS_STRIDE;
    float* m_s   = Ps + 64 * PS_STRIDE;
    float* l_s   = m_s + 64;
    float* al_s  = l_s + 64;
    float* rmx_s = al_s + 64;
    float* rsm_s = rmx_s + 64;
    int*   km_s  = (int*)(rsm_s + 64);

    const int t  = threadIdx.x;
    const int qt = gridDim.x - 1 - blockIdx.x;  // heavy causal tiles first
    const int h  = blockIdx.y;
    const int b  = blockIdx.z;
    const int qs = qt << 6;
    const float scale = 0.08838834764831845f;   // 1/sqrt(128)
    const size_t headoff = (size_t)h * kHD;

    // load Q tile (pre-scaled)
    #pragma unroll
    for (int i = 0; i < 8; ++i) {
        const int idx = t + (i << 8);
        const int r = idx >> 5;
        const int c = (idx & 31) << 2;
        float4 v = *(const float4*)(Q + (size_t)(b * kS + qs + r) * kD + headoff + c);
        float* qp = Qs + r * QS_STRIDE + c;
        qp[0] = v.x * scale; qp[1] = v.y * scale;
        qp[2] = v.z * scale; qp[3] = v.w * scale;
    }
    if (t < 64) { m_s[t] = -1e30f; l_s[t] = 0.f; }

    const int ti = t >> 4;     // row group (shared by S and PV phases)
    const int tj = t & 15;     // col group
    const int i0 = ti << 2;
    const int sj = tj << 2;    // S cols
    const int c0 = tj << 3;    // O cols

    float accO[4][8];
    #pragma unroll
    for (int r = 0; r < 4; ++r)
        #pragma unroll
        for (int c = 0; c < 8; ++c) accO[r][c] = 0.f;

    const int nkt = qt + 1;
    for (int kt = 0; kt < nkt; ++kt) {
        const int ks = kt << 6;
        __syncthreads();   // (A) prior reads of Ks/Vs/Ps complete

        #pragma unroll
        for (int i = 0; i < 8; ++i) {
            const int idx = t + (i << 8);
            const int r = idx >> 5;
            const int c = (idx & 31) << 2;
            const size_t goff = (size_t)(b * kS + ks + r) * kD + headoff + c;
            float4 kv = *(const float4*)(Kg + goff);
            float* kp = Ks + r * KS_STRIDE + c;
            kp[0] = kv.x; kp[1] = kv.y; kp[2] = kv.z; kp[3] = kv.w;
            float4 vv = *(const float4*)(Vg + goff);
            *(float4*)(Vs + r * VS_STRIDE + c) = vv;
        }
        if (t < 64) km_s[t] = am[b * kS + ks + t];
        __syncthreads();   // (B) tiles ready

        // ---- S = (Q*scale) @ K^T, 4x4 per thread ----
        float sv[4][4];
        #pragma unroll
        for (int r = 0; r < 4; ++r)
            #pragma unroll
            for (int c = 0; c < 4; ++c) sv[r][c] = 0.f;

        #pragma unroll 4
        for (int d = 0; d < kHD; ++d) {
            float qv[4], kv[4];
            #pragma unroll
            for (int r = 0; r < 4; ++r) qv[r] = Qs[(i0 + r) * QS_STRIDE + d];
            #pragma unroll
            for (int c = 0; c < 4; ++c) kv[c] = Ks[(sj + c) * KS_STRIDE + d];
            #pragma unroll
            for (int r = 0; r < 4; ++r)
                #pragma unroll
                for (int c = 0; c < 4; ++c)
                    sv[r][c] = fmaf(qv[r], kv[c], sv[r][c]);
        }

        // ---- mask + row max ----
        float rmx[4];
        #pragma unroll
        for (int r = 0; r < 4; ++r) {
            const int gq = qs + i0 + r;
            rmx[r] = -1e30f;
            #pragma unroll
            for (int c = 0; c < 4; ++c) {
                const int gk = ks + sj + c;
                const bool ok = (gk <= gq) && (km_s[sj + c] != 0);
                sv[r][c] = ok ? sv[r][c] : -1e30f;
                rmx[r] = fmaxf(rmx[r], sv[r][c]);
            }
        }
        #pragma unroll
        for (int o = 8; o; o >>= 1)
            #pragma unroll
            for (int r = 0; r < 4; ++r)
                rmx[r] = fmaxf(rmx[r], __shfl_xor_sync(0xffffffffu, rmx[r], o));
        if (tj == 0) {
            #pragma unroll
            for (int r = 0; r < 4; ++r) rmx_s[i0 + r] = rmx[r];
        }
        __syncthreads();   // (C)

        if (t < 64) {
            const float mo = m_s[t];
            const float mn = fmaxf(mo, rmx_s[t]);
            al_s[t] = __expf(mo - mn);
            m_s[t]  = mn;
        }
        __syncthreads();   // (D)

        // ---- p = exp(s - m), row sums, stash P ----
        float rs[4] = {0.f, 0.f, 0.f, 0.f};
        #pragma unroll
        for (int r = 0; r < 4; ++r) {
            const float mn = m_s[i0 + r];
            #pragma unroll
            for (int c = 0; c < 4; ++c) {
                const float p = __expf(sv[r][c] - mn);
                rs[r] += p;
                Ps[(i0 + r) * PS_STRIDE + sj + c] = p;
            }
        }
        #pragma unroll
        for (int o = 8; o; o >>= 1)
            #pragma unroll
            for (int r = 0; r < 4; ++r)
                rs[r] += __shfl_xor_sync(0xffffffffu, rs[r], o);
        if (tj == 0) {
            #pragma unroll
            for (int r = 0; r < 4; ++r) rsm_s[i0 + r] = rs[r];
        }
        __syncthreads();   // (E) P + row sums ready

        if (t < 64) l_s[t] = l_s[t] * al_s[t] + rsm_s[t];

        // ---- rescale + O += P @ V ----
        float alr[4];
        #pragma unroll
        for (int r = 0; r < 4; ++r) alr[r] = al_s[i0 + r];
        #pragma unroll
        for (int r = 0; r < 4; ++r)
            #pragma unroll
            for (int c = 0; c < 8; ++c) accO[r][c] *= alr[r];

        #pragma unroll 2
        for (int j = 0; j < 64; ++j) {
            float pv[4];
            #pragma unroll
            for (int r = 0; r < 4; ++r) pv[r] = Ps[(i0 + r) * PS_STRIDE + j];
            const float4 v0 = *(const float4*)(Vs + j * VS_STRIDE + c0);
            const float4 v1 = *(const float4*)(Vs + j * VS_STRIDE + c0 + 4);
            #pragma unroll
            for (int r = 0; r < 4; ++r) {
                accO[r][0] = fmaf(pv[r], v0.x, accO[r][0]);
                accO[r][1] = fmaf(pv[r], v0.y, accO[r][1]);
                accO[r][2] = fmaf(pv[r], v0.z, accO[r][2]);
                accO[r][3] = fmaf(pv[r], v0.w, accO[r][3]);
                accO[r][4] = fmaf(pv[r], v1.x, accO[r][4]);
                accO[r][5] = fmaf(pv[r], v1.y, accO[r][5]);
                accO[r][6] = fmaf(pv[r], v1.z, accO[r][6]);
                accO[r][7] = fmaf(pv[r], v1.w, accO[r][7]);
            }
        }
    }
    __syncthreads();   // (F) final l_s visible

    #pragma unroll
    for (int r = 0; r < 4; ++r) {
        const float inv = 1.0f / l_s[i0 + r];
        const size_t off = (size_t)(b * kS + qs + i0 + r) * kD + headoff + c0;
        float4 o0, o1;
        o0.x = accO[r][0] * inv; o0.y = accO[r][1] * inv;
        o0.z = accO[r][2] * inv; o0.w = accO[r][3] * inv;
        o1.x = accO[r][4] * inv; o1.y = accO[r][5] * inv;
        o1.z = accO[r][6] * inv; o1.w = accO[r][7] * inv;
        *(float4*)(Og + off)     = o0;
        *(float4*)(Og + off + 4) = o1;
    }
}

// ===========================================================================
// launch
// ===========================================================================
extern "C" void kernel_launch(void* const* d_in, const int* in_sizes, int n_in,
                              void* d_out, int out_size)
{
    (void)in_sizes; (void)n_in; (void)out_size;

    const float* x     = (const float*)d_in[0];
    const int*   amask = (const int*)  d_in[1];
    const float* ln1_g = (const float*)d_in[2];
    const float* ln1_b = (const float*)d_in[3];
    const float* wq    = (const float*)d_in[4];
    const float* bq    = (const float*)d_in[5];
    const float* wk    = (const float*)d_in[6];
    const float* bk    = (const float*)d_in[7];
    const float* wv    = (const float*)d_in[8];
    const float* bv    = (const float*)d_in[9];
    const float* wo    = (const float*)d_in[10];
    const float* bo    = (const float*)d_in[11];
    const float* ln2_g = (const float*)d_in[12];
    const float* ln2_b = (const float*)d_in[13];
    const float* w1    = (const float*)d_in[14];
    const float* b1    = (const float*)d_in[15];
    const float* w2    = (const float*)d_in[16];
    const float* b2    = (const float*)d_in[17];
    float*       out   = (float*)d_out;

    float *ph, *pq, *pk, *pv, *px1, *pff;
    cudaGetSymbolAddress((void**)&ph,  g_buf_h);
    cudaGetSymbolAddress((void**)&pq,  g_buf_q);
    cudaGetSymbolAddress((void**)&pk,  g_buf_k);
    cudaGetSymbolAddress((void**)&pv,  g_buf_v);
    cudaGetSymbolAddress((void**)&px1, g_buf_x1);
    cudaGetSymbolAddress((void**)&pff, g_buf_ff);

    cudaFuncSetAttribute(flash_kernel,
                         cudaFuncAttributeMaxDynamicSharedMemorySize,
                         FLASH_SMEM_BYTES);

    const dim3 blk(256);
    const dim3 g_d (kD   / 128, kRows / 128);   // (16, 32)
    const dim3 g_ff(kDFF / 128, kRows / 128);   // (64, 32)

    // 1) h = LN1(x)
    ln_kernel<<<kRows, blk>>>(x, ln1_g, ln1_b, ph);
    // 2) q,k,v = h @ w{q,k,v} + b{q,k,v}
    sgemm_kernel<0><<<g_d, blk>>>(ph, wq, bq, nullptr, pq, kRows, kD, kD);
    sgemm_kernel<0><<<g_d, blk>>>(ph, wk, bk, nullptr, pk, kRows, kD, kD);
    sgemm_kernel<0><<<g_d, blk>>>(ph, wv, bv, nullptr, pv, kRows, kD, kD);
    // 3) attn (causal flash) -> reuse h buffer
    flash_kernel<<<dim3(kS / 64, kH, kB), blk, FLASH_SMEM_BYTES>>>(pq, pk, pv, amask, ph);
    // 4) x1 = x + attn @ wo + bo
    sgemm_kernel<1><<<g_d, blk>>>(ph, wo, bo, x, px1, kRows, kD, kD);
    // 5) h2 = LN2(x1) -> reuse q buffer
    ln_kernel<<<kRows, blk>>>(px1, ln2_g, ln2_b, pq);
    // 6) ff = gelu(h2 @ w1 + b1)
    sgemm_kernel<2><<<g_ff, blk>>>(pq, w1, b1, nullptr, pff, kRows, kDFF, kD);
    // 7) out = x1 + ff @ w2 + b2
    sgemm_kernel<1><<<g_d, blk>>>(pff, w2, b2, px1, out, kRows, kD, kDFF);
}

// round 13
// speedup vs baseline: 1.0024x; 1.0024x over previous
#include <cuda_runtime.h>
#include <math.h>
#include <stdint.h>

// ---------------- problem dims (hardcoded, verified vs reference) ----------
static constexpr int kB   = 2;
static constexpr int kS   = 2048;
static constexpr int kD   = 2048;
static constexpr int kH   = 16;
static constexpr int kHD  = 128;     // kD / kH
static constexpr int kDFF = 8192;    // 4 * kD
static constexpr int kRows = kB * kS;            // 4096
static constexpr float kEPS = 1e-5f;

// ---------------- scratch (device globals; no allocations allowed) --------
__device__ float g_buf_h [(size_t)kRows * kD];    // LN1 out -> later attn out
__device__ float g_buf_q [(size_t)kRows * kD];    // q -> later h2 (LN2 out)
__device__ float g_buf_k [(size_t)kRows * kD];
__device__ float g_buf_v [(size_t)kRows * kD];
__device__ float g_buf_x1[(size_t)kRows * kD];    // x + attn@wo
__device__ float g_buf_ff[(size_t)kRows * kDFF];  // GELU(h2@w1+b1)

// ===========================================================================
// LayerNorm: one block per row, D=2048, 256 threads, 8 floats/thread in regs
// ===========================================================================
__global__ void __launch_bounds__(256) ln_kernel(const float* __restrict__ x,
                                                 const float* __restrict__ g,
                                                 const float* __restrict__ b,
                                                 float* __restrict__ y)
{
    __shared__ float red1[8];
    __shared__ float red2[8];
    __shared__ float bc1, bc2;

    const int row = blockIdx.x;
    const int t   = threadIdx.x;

    const float4* xr = (const float4*)(x + (size_t)row * kD);
    float4 v0 = xr[t];
    float4 v1 = xr[t + 256];

    float s = v0.x + v0.y + v0.z + v0.w + v1.x + v1.y + v1.z + v1.w;
    #pragma unroll
    for (int o = 16; o; o >>= 1) s += __shfl_xor_sync(0xffffffffu, s, o);
    if ((t & 31) == 0) red1[t >> 5] = s;
    __syncthreads();
    if (t == 0) {
        float tot = 0.f;
        #pragma unroll
        for (int i = 0; i < 8; ++i) tot += red1[i];
        bc1 = tot * (1.0f / kD);
    }
    __syncthreads();
    const float mu = bc1;

    float d0 = v0.x - mu, d1 = v0.y - mu, d2 = v0.z - mu, d3 = v0.w - mu;
    float d4 = v1.x - mu, d5 = v1.y - mu, d6 = v1.z - mu, d7 = v1.w - mu;
    float ss = d0*d0 + d1*d1 + d2*d2 + d3*d3 + d4*d4 + d5*d5 + d6*d6 + d7*d7;
    #pragma unroll
    for (int o = 16; o; o >>= 1) ss += __shfl_xor_sync(0xffffffffu, ss, o);
    if ((t & 31) == 0) red2[t >> 5] = ss;
    __syncthreads();
    if (t == 0) {
        float tot = 0.f;
        #pragma unroll
        for (int i = 0; i < 8; ++i) tot += red2[i];
        bc2 = rsqrtf(tot * (1.0f / kD) + kEPS);
    }
    __syncthreads();
    const float rs = bc2;

    const float4* gr = (const float4*)g;
    const float4* br = (const float4*)b;
    float4 g0 = gr[t], g1 = gr[t + 256];
    float4 b0 = br[t], b1 = br[t + 256];

    float4 o0, o1;
    o0.x = d0 * rs * g0.x + b0.x;  o0.y = d1 * rs * g0.y + b0.y;
    o0.z = d2 * rs * g0.z + b0.z;  o0.w = d3 * rs * g0.w + b0.w;
    o1.x = d4 * rs * g1.x + b1.x;  o1.y = d5 * rs * g1.y + b1.y;
    o1.z = d6 * rs * g1.z + b1.z;  o1.w = d7 * rs * g1.w + b1.w;

    float4* yr = (float4*)(y + (size_t)row * kD);
    yr[t]       = o0;
    yr[t + 256] = o1;
}

// ===========================================================================
// SGEMM: C[M,N] = A[M,K] @ W[K,N] (+ epilogue)
//   128x128 block tile, 16 k-tile, 256 threads, 8x8 microtile, double buffer.
//   EPI 0: +bias   EPI 1: +bias+res   EPI 2: gelu(+bias)
//   Requires M%128==0, N%128==0, K%16==0 (true for all uses here).
// ===========================================================================
__device__ __forceinline__ float gelu_f(float v) {
    return 0.5f * v * (1.0f + erff(v * 0.70710678118654752440f));
}

template<int EPI>
__global__ void __launch_bounds__(256, 2) sgemm_kernel(
    const float* __restrict__ A, const float* __restrict__ W,
    const float* __restrict__ bias, const float* __restrict__ res,
    float* __restrict__ C, int M, int N, int K)
{
    __shared__ __align__(16) float As[2][16][132];   // transposed A tile
    __shared__ __align__(16) float Bs[2][16][132];

    const int t  = threadIdx.x;
    const int bm = blockIdx.y << 7;
    const int bn = blockIdx.x << 7;

    // global load mapping
    const int ar = t >> 2;            // 0..63
    const int ac = (t & 3) << 2;      // 0,4,8,12
    const int br = t >> 5;            // 0..7
    const int bc = (t & 31) << 2;     // 0..124
    const float* Ap  = A + (size_t)(bm + ar) * K + ac;
    const float* Ap2 = Ap + (size_t)64 * K;
    const float* Bp  = W + (size_t)br * N + bn + bc;
    const float* Bp2 = Bp + (size_t)8 * N;

    // compute mapping
    const int tm = (t & 15) << 3;     // row offset
    const int tn = (t >> 4) << 3;     // col offset

    float acc[8][8];
    #pragma unroll
    for (int i = 0; i < 8; ++i)
        #pragma unroll
        for (int j = 0; j < 8; ++j) acc[i][j] = 0.f;

    // prologue: tile 0 -> smem buf 0
    {
        float4 a0 = *(const float4*)Ap;
        float4 a1 = *(const float4*)Ap2;
        float4 b0 = *(const float4*)Bp;
        float4 b1 = *(const float4*)Bp2;
        As[0][ac+0][ar]    = a0.x; As[0][ac+1][ar]    = a0.y;
        As[0][ac+2][ar]    = a0.z; As[0][ac+3][ar]    = a0.w;
        As[0][ac+0][ar+64] = a1.x; As[0][ac+1][ar+64] = a1.y;
        As[0][ac+2][ar+64] = a1.z; As[0][ac+3][ar+64] = a1.w;
        *(float4*)&Bs[0][br][bc]     = b0;
        *(float4*)&Bs[0][br + 8][bc] = b1;
    }
    __syncthreads();

    const int KT = K >> 4;
    int cur = 0;
    for (int kt = 0; kt < KT; ++kt) {
        float4 na0, na1, nb0, nb1;
        const bool has_next = (kt + 1 < KT);
        if (has_next) {
            const float* ap = Ap + ((kt + 1) << 4);
            na0 = *(const float4*)ap;
            na1 = *(const float4*)(ap + (size_t)64 * K);
            const float* bp = Bp + (size_t)((kt + 1) << 4) * N;
            nb0 = *(const float4*)bp;
            nb1 = *(const float4*)(bp + (size_t)8 * N);
        }

        #pragma unroll
        for (int k = 0; k < 16; ++k) {
            float a[8], w[8];
            *(float4*)&a[0] = *(const float4*)&As[cur][k][tm];
            *(float4*)&a[4] = *(const float4*)&As[cur][k][tm + 4];
            *(float4*)&w[0] = *(const float4*)&Bs[cur][k][tn];
            *(float4*)&w[4] = *(const float4*)&Bs[cur][k][tn + 4];
            #pragma unroll
            for (int i = 0; i < 8; ++i)
                #pragma unroll
                for (int j = 0; j < 8; ++j)
                    acc[i][j] = fmaf(a[i], w[j], acc[i][j]);
        }

        if (has_next) {
            const int nxt = cur ^ 1;
            As[nxt][ac+0][ar]    = na0.x; As[nxt][ac+1][ar]    = na0.y;
            As[nxt][ac+2][ar]    = na0.z; As[nxt][ac+3][ar]    = na0.w;
            As[nxt][ac+0][ar+64] = na1.x; As[nxt][ac+1][ar+64] = na1.y;
            As[nxt][ac+2][ar+64] = na1.z; As[nxt][ac+3][ar+64] = na1.w;
            *(float4*)&Bs[nxt][br][bc]     = nb0;
            *(float4*)&Bs[nxt][br + 8][bc] = nb1;
            __syncthreads();
            cur = nxt;
        }
    }

    // epilogue
    float bv[8];
    *(float4*)&bv[0] = *(const float4*)&bias[bn + tn];
    *(float4*)&bv[4] = *(const float4*)&bias[bn + tn + 4];

    #pragma unroll
    for (int i = 0; i < 8; ++i) {
        const size_t off = (size_t)(bm + tm + i) * N + bn + tn;
        float o[8];
        #pragma unroll
        for (int j = 0; j < 8; ++j) o[j] = acc[i][j] + bv[j];
        if (EPI == 1) {
            float rv[8];
            *(float4*)&rv[0] = *(const float4*)(res + off);
            *(float4*)&rv[4] = *(const float4*)(res + off + 4);
            #pragma unroll
            for (int j = 0; j < 8; ++j) o[j] += rv[j];
        } else if (EPI == 2) {
            #pragma unroll
            for (int j = 0; j < 8; ++j) o[j] = gelu_f(o[j]);
        }
        *(float4*)(C + off)     = *(float4*)&o[0];
        *(float4*)(C + off + 4) = *(float4*)&o[4];
    }
}

// ===========================================================================
// Flash attention (causal + key-pad mask), fp32, online softmax.
//   Per block: one (b, h, q-tile of 64). BK=64, HD=128. 256 threads.
//   Q/K/V layout: [B, S, H*HD] (head h lives at cols h*128..h*128+127).
// ===========================================================================
static constexpr int QS_STRIDE = 129;
static constexpr int KS_STRIDE = 129;
static constexpr int VS_STRIDE = 132;  // 16B-aligned rows for float4 loads
static constexpr int PS_STRIDE = 65;
static constexpr int FLASH_SMEM_FLOATS =
    64 * QS_STRIDE + 64 * KS_STRIDE + 64 * VS_STRIDE + 64 * PS_STRIDE + 5 * 64 + 64;
static constexpr int FLASH_SMEM_BYTES = FLASH_SMEM_FLOATS * 4; // 118016

__global__ void __launch_bounds__(256) flash_kernel(
    const float* __restrict__ Q, const float* __restrict__ Kg,
    const float* __restrict__ Vg, const int* __restrict__ am,
    float* __restrict__ Og)
{
    extern __shared__ float sm[];
    float* Qs    = sm;
    float* Ks    = Qs + 64 * QS_STRIDE;
    float* Vs    = Ks + 64 * KS_STRIDE;
    float* Ps    = Vs + 64 * VS_STRIDE;
    float* m_s   = Ps + 64 * PS_STRIDE;
    float* l_s   = m_s + 64;
    float* al_s  = l_s + 64;
    float* rmx_s = al_s + 64;
    float* rsm_s = rmx_s + 64;
    int*   km_s  = (int*)(rsm_s + 64);

    const int t  = threadIdx.x;
    const int qt = gridDim.x - 1 - blockIdx.x;  // heavy causal tiles first
    const int h  = blockIdx.y;
    const int b  = blockIdx.z;
    const int qs = qt << 6;
    const float scale = 0.08838834764831845f;   // 1/sqrt(128)
    const size_t headoff = (size_t)h * kHD;

    // load Q tile (pre-scaled)
    #pragma unroll
    for (int i = 0; i < 8; ++i) {
        const int idx = t + (i << 8);
        const int r = idx >> 5;
        const int c = (idx & 31) << 2;
        float4 v = *(const float4*)(Q + (size_t)(b * kS + qs + r) * kD + headoff + c);
        float* qp = Qs + r * QS_STRIDE + c;
        qp[0] = v.x * scale; qp[1] = v.y * scale;
        qp[2] = v.z * scale; qp[3] = v.w * scale;
    }
    if (t < 64) { m_s[t] = -1e30f; l_s[t] = 0.f; }

    const int ti = t >> 4;     // row group (shared by S and PV phases)
    const int tj = t & 15;     // col group
    const int i0 = ti << 2;
    const int sj = tj << 2;    // S cols
    const int c0 = tj << 3;    // O cols

    float accO[4][8];
    #pragma unroll
    for (int r = 0; r < 4; ++r)
        #pragma unroll
        for (int c = 0; c < 8; ++c) accO[r][c] = 0.f;

    const int nkt = qt + 1;
    for (int kt = 0; kt < nkt; ++kt) {
        const int ks = kt << 6;
        __syncthreads();   // (A) prior reads of Ks/Vs/Ps complete

        #pragma unroll
        for (int i = 0; i < 8; ++i) {
            const int idx = t + (i << 8);
            const int r = idx >> 5;
            const int c = (idx & 31) << 2;
            const size_t goff = (size_t)(b * kS + ks + r) * kD + headoff + c;
            float4 kv = *(const float4*)(Kg + goff);
            float* kp = Ks + r * KS_STRIDE + c;
            kp[0] = kv.x; kp[1] = kv.y; kp[2] = kv.z; kp[3] = kv.w;
            float4 vv = *(const float4*)(Vg + goff);
            *(float4*)(Vs + r * VS_STRIDE + c) = vv;
        }
        if (t < 64) km_s[t] = am[b * kS + ks + t];
        __syncthreads();   // (B) tiles ready

        // ---- S = (Q*scale) @ K^T, 4x4 per thread ----
        float sv[4][4];
        #pragma unroll
        for (int r = 0; r < 4; ++r)
            #pragma unroll
            for (int c = 0; c < 4; ++c) sv[r][c] = 0.f;

        #pragma unroll 4
        for (int d = 0; d < kHD; ++d) {
            float qv[4], kv[4];
            #pragma unroll
            for (int r = 0; r < 4; ++r) qv[r] = Qs[(i0 + r) * QS_STRIDE + d];
            #pragma unroll
            for (int c = 0; c < 4; ++c) kv[c] = Ks[(sj + c) * KS_STRIDE + d];
            #pragma unroll
            for (int r = 0; r < 4; ++r)
                #pragma unroll
                for (int c = 0; c < 4; ++c)
                    sv[r][c] = fmaf(qv[r], kv[c], sv[r][c]);
        }

        // ---- mask + row max ----
        float rmx[4];
        #pragma unroll
        for (int r = 0; r < 4; ++r) {
            const int gq = qs + i0 + r;
            rmx[r] = -1e30f;
            #pragma unroll
            for (int c = 0; c < 4; ++c) {
                const int gk = ks + sj + c;
                const bool ok = (gk <= gq) && (km_s[sj + c] != 0);
                sv[r][c] = ok ? sv[r][c] : -1e30f;
                rmx[r] = fmaxf(rmx[r], sv[r][c]);
            }
        }
        #pragma unroll
        for (int o = 8; o; o >>= 1)
            #pragma unroll
            for (int r = 0; r < 4; ++r)
                rmx[r] = fmaxf(rmx[r], __shfl_xor_sync(0xffffffffu, rmx[r], o));
        if (tj == 0) {
            #pragma unroll
            for (int r = 0; r < 4; ++r) rmx_s[i0 + r] = rmx[r];
        }
        __syncthreads();   // (C)

        if (t < 64) {
            const float mo = m_s[t];
            const float mn = fmaxf(mo, rmx_s[t]);
            al_s[t] = __expf(mo - mn);
            m_s[t]  = mn;
        }
        __syncthreads();   // (D)

        // ---- p = exp(s - m), row sums, stash P ----
        float rs[4] = {0.f, 0.f, 0.f, 0.f};
        #pragma unroll
        for (int r = 0; r < 4; ++r) {
            const float mn = m_s[i0 + r];
            #pragma unroll
            for (int c = 0; c < 4; ++c) {
                const float p = __expf(sv[r][c] - mn);
                rs[r] += p;
                Ps[(i0 + r) * PS_STRIDE + sj + c] = p;
            }
        }
        #pragma unroll
        for (int o = 8; o; o >>= 1)
            #pragma unroll
            for (int r = 0; r < 4; ++r)
                rs[r] += __shfl_xor_sync(0xffffffffu, rs[r], o);
        if (tj == 0) {
            #pragma unroll
            for (int r = 0; r < 4; ++r) rsm_s[i0 + r] = rs[r];
        }
        __syncthreads();   // (E) P + row sums ready

        if (t < 64) l_s[t] = l_s[t] * al_s[t] + rsm_s[t];

        // ---- rescale + O += P @ V ----
        float alr[4];
        #pragma unroll
        for (int r = 0; r < 4; ++r) alr[r] = al_s[i0 + r];
        #pragma unroll
        for (int r = 0; r < 4; ++r)
            #pragma unroll
            for (int c = 0; c < 8; ++c) accO[r][c] *= alr[r];

        #pragma unroll 2
        for (int j = 0; j < 64; ++j) {
            float pv[4];
            #pragma unroll
            for (int r = 0; r < 4; ++r) pv[r] = Ps[(i0 + r) * PS_STRIDE + j];
            const float4 v0 = *(const float4*)(Vs + j * VS_STRIDE + c0);
            const float4 v1 = *(const float4*)(Vs + j * VS_STRIDE + c0 + 4);
            #pragma unroll
            for (int r = 0; r < 4; ++r) {
                accO[r][0] = fmaf(pv[r], v0.x, accO[r][0]);
                accO[r][1] = fmaf(pv[r], v0.y, accO[r][1]);
                accO[r][2] = fmaf(pv[r], v0.z, accO[r][2]);
                accO[r][3] = fmaf(pv[r], v0.w, accO[r][3]);
                accO[r][4] = fmaf(pv[r], v1.x, accO[r][4]);
                accO[r][5] = fmaf(pv[r], v1.y, accO[r][5]);
                accO[r][6] = fmaf(pv[r], v1.z, accO[r][6]);
                accO[r][7] = fmaf(pv[r], v1.w, accO[r][7]);
            }
        }
    }
    __syncthreads();   // (F) final l_s visible

    #pragma unroll
    for (int r = 0; r < 4; ++r) {
        const float inv = 1.0f / l_s[i0 + r];
        const size_t off = (size_t)(b * kS + qs + i0 + r) * kD + headoff + c0;
        float4 o0, o1;
        o0.x = accO[r][0] * inv; o0.y = accO[r][1] * inv;
        o0.z = accO[r][2] * inv; o0.w = accO[r][3] * inv;
        o1.x = accO[r][4] * inv; o1.y = accO[r][5] * inv;
        o1.z = accO[r][6] * inv; o1.w = accO[r][7] * inv;
        *(float4*)(Og + off)     = o0;
        *(float4*)(Og + off + 4) = o1;
    }
}

// ===========================================================================
// launch
// ===========================================================================
extern "C" void kernel_launch(void* const* d_in, const int* in_sizes, int n_in,
                              void* d_out, int out_size)
{
    (void)in_sizes; (void)n_in; (void)out_size;

    const float* x     = (const float*)d_in[0];
    const int*   amask = (const int*)  d_in[1];
    const float* ln1_g = (const float*)d_in[2];
    const float* ln1_b = (const float*)d_in[3];
    const float* wq    = (const float*)d_in[4];
    const float* bq    = (const float*)d_in[5];
    const float* wk    = (const float*)d_in[6];
    const float* bk    = (const float*)d_in[7];
    const float* wv    = (const float*)d_in[8];
    const float* bv    = (const float*)d_in[9];
    const float* wo    = (const float*)d_in[10];
    const float* bo    = (const float*)d_in[11];
    const float* ln2_g = (const float*)d_in[12];
    const float* ln2_b = (const float*)d_in[13];
    const float* w1    = (const float*)d_in[14];
    const float* b1    = (const float*)d_in[15];
    const float* w2    = (const float*)d_in[16];
    const float* b2    = (const float*)d_in[17];
    float*       out   = (float*)d_out;

    float *ph, *pq, *pk, *pv, *px1, *pff;
    cudaGetSymbolAddress((void**)&ph,  g_buf_h);
    cudaGetSymbolAddress((void**)&pq,  g_buf_q);
    cudaGetSymbolAddress((void**)&pk,  g_buf_k);
    cudaGetSymbolAddress((void**)&pv,  g_buf_v);
    cudaGetSymbolAddress((void**)&px1, g_buf_x1);
    cudaGetSymbolAddress((void**)&pff, g_buf_ff);

    cudaFuncSetAttribute(flash_kernel,
                         cudaFuncAttributeMaxDynamicSharedMemorySize,
                         FLASH_SMEM_BYTES);

    const dim3 blk(256);
    const dim3 g_d (kD   / 128, kRows / 128);   // (16, 32)
    const dim3 g_ff(kDFF / 128, kRows / 128);   // (64, 32)

    // 1) h = LN1(x)
    ln_kernel<<<kRows, blk>>>(x, ln1_g, ln1_b, ph);
    // 2) q,k,v = h @ w{q,k,v} + b{q,k,v}
    sgemm_kernel<0><<<g_d, blk>>>(ph, wq, bq, nullptr, pq, kRows, kD, kD);
    sgemm_kernel<0><<<g_d, blk>>>(ph, wk, bk, nullptr, pk, kRows, kD, kD);
    sgemm_kernel<0><<<g_d, blk>>>(ph, wv, bv, nullptr, pv, kRows, kD, kD);
    // 3) attn (causal flash) -> reuse h buffer
    flash_kernel<<<dim3(kS / 64, kH, kB), blk, FLASH_SMEM_BYTES>>>(pq, pk, pv, amask, ph);
    // 4) x1 = x + attn @ wo + bo
    sgemm_kernel<1><<<g_d, blk>>>(ph, wo, bo, x, px1, kRows, kD, kD);
    // 5) h2 = LN2(x1) -> reuse q buffer
    ln_kernel<<<kRows, blk>>>(px1, ln2_g, ln2_b, pq);
    // 6) ff = gelu(h2 @ w1 + b1)
    sgemm_kernel<2><<<g_ff, blk>>>(pq, w1, b1, nullptr, pff, kRows, kDFF, kD);
    // 7) out = x1 + ff @ w2 + b2
    sgemm_kernel<1><<<g_d, blk>>>(pff, w2, b2, px1, out, kRows, kD, kDFF);
}